// round 2
// baseline (speedup 1.0000x reference)
#include <cuda_runtime.h>
#include <cuda_bf16.h>
#include <cstdint>

// soft_to_hard_quantize: N=524288 vectors of D=16 floats, M=64 codewords.
// logit_m = (10*dot(x,r_m) - 5*||r_m||^2) * log2(e)   (||x||^2 cancels in softmax)
// Online (chunked) softmax over m, weighted codeword sum.
// V=2 vectors per thread to amortize codebook LDS; chunk=16 keeps logits in regs.

#define MCODE 64
#define DVEC  16
#define TPB   256
#define VPT   2
#define CHUNK 16

typedef unsigned long long u64;

__device__ __forceinline__ u64 fma2(u64 a, u64 b, u64 c) {
    u64 d;
    asm("fma.rn.f32x2 %0, %1, %2, %3;" : "=l"(d) : "l"(a), "l"(b), "l"(c));
    return d;
}
__device__ __forceinline__ u64 mul2(u64 a, u64 b) {
    u64 d;
    asm("mul.rn.f32x2 %0, %1, %2;" : "=l"(d) : "l"(a), "l"(b));
    return d;
}
__device__ __forceinline__ u64 pack2(float lo, float hi) {
    u64 r;
    asm("mov.b64 %0, {%1, %2};" : "=l"(r) : "f"(lo), "f"(hi));
    return r;
}
__device__ __forceinline__ void unpack2(u64 v, float& lo, float& hi) {
    asm("mov.b64 {%0, %1}, %2;" : "=f"(lo), "=f"(hi) : "l"(v));
}
__device__ __forceinline__ float ex2f(float x) {
    float r;
    asm("ex2.approx.ftz.f32 %0, %1;" : "=f"(r) : "f"(x));
    return r;
}

__global__ __launch_bounds__(TPB, 2)
void stq_kernel(const float* __restrict__ x,
                const float* __restrict__ ref,
                float* __restrict__ out,
                int nvec) {
    // Codebook as packed f32 pairs: rp[m*8+p] = (r_m[2p], r_m[2p+1]).
    __shared__ u64  rp[MCODE * 8];
    __shared__ float b2[MCODE];   // -5*log2(e)*||r_m||^2

    const int tid = threadIdx.x;

    if (tid < 256) {
        ulonglong2 q = reinterpret_cast<const ulonglong2*>(ref)[tid];
        rp[2 * tid + 0] = q.x;
        rp[2 * tid + 1] = q.y;
    }
    if (tid < MCODE) {
        float s = 0.0f;
        #pragma unroll
        for (int i = 0; i < DVEC; i++) {
            float r = ref[tid * DVEC + i];
            s = fmaf(r, r, s);
        }
        b2[tid] = -7.2134752044448169f * s;   // -5*log2(e)
    }
    __syncthreads();

    const int v0 = blockIdx.x * (TPB * VPT) + tid;   // vector A
    const int v1 = v0 + TPB;                          // vector B
    if (v0 >= nvec) return;
    const bool haveB = (v1 < nvec);

    // Load both vectors: 16 floats = 8 packed pairs each (4x LDG.128).
    u64 xa[8], xb[8];
    {
        const ulonglong2* pa = reinterpret_cast<const ulonglong2*>(x + (size_t)v0 * DVEC);
        #pragma unroll
        for (int i = 0; i < 4; i++) {
            ulonglong2 t = pa[i];
            xa[2 * i + 0] = t.x;
            xa[2 * i + 1] = t.y;
        }
        const ulonglong2* pb = reinterpret_cast<const ulonglong2*>(
            x + (size_t)(haveB ? v1 : v0) * DVEC);
        #pragma unroll
        for (int i = 0; i < 4; i++) {
            ulonglong2 t = pb[i];
            xb[2 * i + 0] = t.x;
            xb[2 * i + 1] = t.y;
        }
    }

    float rm0 = -1e30f, rm1 = -1e30f;    // running max (log2 domain)
    float s0 = 0.0f, s1 = 0.0f;          // running denom
    u64 za[8], zb[8];
    #pragma unroll
    for (int p = 0; p < 8; p++) { za[p] = 0ULL; zb[p] = 0ULL; }

    const ulonglong2* rp2 = reinterpret_cast<const ulonglong2*>(rp);

    #pragma unroll 1
    for (int c = 0; c < MCODE / CHUNK; c++) {
        const int mb = c * CHUNK;

        // ---- chunk logits (kept in registers) ----
        float l0[CHUNK], l1[CHUNK];
        #pragma unroll
        for (int j = 0; j < CHUNK; j++) {
            const int m = mb + j;
            ulonglong2 q0 = rp2[m * 4 + 0];
            ulonglong2 q1 = rp2[m * 4 + 1];
            ulonglong2 q2 = rp2[m * 4 + 2];
            ulonglong2 q3 = rp2[m * 4 + 3];

            u64 a = fma2(xa[0], q0.x, 0ULL);
            a = fma2(xa[1], q0.y, a);
            a = fma2(xa[2], q1.x, a);
            a = fma2(xa[3], q1.y, a);
            a = fma2(xa[4], q2.x, a);
            a = fma2(xa[5], q2.y, a);
            a = fma2(xa[6], q3.x, a);
            a = fma2(xa[7], q3.y, a);

            u64 b = fma2(xb[0], q0.x, 0ULL);
            b = fma2(xb[1], q0.y, b);
            b = fma2(xb[2], q1.x, b);
            b = fma2(xb[3], q1.y, b);
            b = fma2(xb[4], q2.x, b);
            b = fma2(xb[5], q2.y, b);
            b = fma2(xb[6], q3.x, b);
            b = fma2(xb[7], q3.y, b);

            const float bias = b2[m];
            float lo, hi;
            unpack2(a, lo, hi);
            l0[j] = fmaf(14.426950408889634f, lo + hi, bias);  // 10*log2(e)
            unpack2(b, lo, hi);
            l1[j] = fmaf(14.426950408889634f, lo + hi, bias);
        }

        // ---- chunk max (4 parallel chains each) ----
        float a0 = fmaxf(l0[0], l0[4]), a1 = fmaxf(l0[1], l0[5]);
        float a2 = fmaxf(l0[2], l0[6]), a3 = fmaxf(l0[3], l0[7]);
        a0 = fmaxf(a0, fmaxf(l0[8], l0[12]));
        a1 = fmaxf(a1, fmaxf(l0[9], l0[13]));
        a2 = fmaxf(a2, fmaxf(l0[10], l0[14]));
        a3 = fmaxf(a3, fmaxf(l0[11], l0[15]));
        const float cm0 = fmaxf(fmaxf(a0, a1), fmaxf(a2, a3));

        float d0 = fmaxf(l1[0], l1[4]), d1 = fmaxf(l1[1], l1[5]);
        float d2 = fmaxf(l1[2], l1[6]), d3 = fmaxf(l1[3], l1[7]);
        d0 = fmaxf(d0, fmaxf(l1[8], l1[12]));
        d1 = fmaxf(d1, fmaxf(l1[9], l1[13]));
        d2 = fmaxf(d2, fmaxf(l1[10], l1[14]));
        d3 = fmaxf(d3, fmaxf(l1[11], l1[15]));
        const float cm1 = fmaxf(fmaxf(d0, d1), fmaxf(d2, d3));

        // ---- rescale accumulators to new running max ----
        const float nm0 = fmaxf(rm0, cm0);
        const float nm1 = fmaxf(rm1, cm1);
        const float cr0 = ex2f(rm0 - nm0);
        const float cr1 = ex2f(rm1 - nm1);
        rm0 = nm0; rm1 = nm1;
        s0 *= cr0; s1 *= cr1;
        const u64 cp0 = pack2(cr0, cr0);
        const u64 cp1 = pack2(cr1, cr1);
        #pragma unroll
        for (int p = 0; p < 8; p++) {
            za[p] = mul2(za[p], cp0);
            zb[p] = mul2(zb[p], cp1);
        }

        // ---- accumulate exp-weighted codewords ----
        #pragma unroll
        for (int j = 0; j < CHUNK; j++) {
            const int m = mb + j;
            const float e0 = ex2f(l0[j] - nm0);
            const float e1 = ex2f(l1[j] - nm1);
            s0 += e0; s1 += e1;
            const u64 ep0 = pack2(e0, e0);
            const u64 ep1 = pack2(e1, e1);
            ulonglong2 q0 = rp2[m * 4 + 0];
            ulonglong2 q1 = rp2[m * 4 + 1];
            ulonglong2 q2 = rp2[m * 4 + 2];
            ulonglong2 q3 = rp2[m * 4 + 3];
            za[0] = fma2(ep0, q0.x, za[0]);  zb[0] = fma2(ep1, q0.x, zb[0]);
            za[1] = fma2(ep0, q0.y, za[1]);  zb[1] = fma2(ep1, q0.y, zb[1]);
            za[2] = fma2(ep0, q1.x, za[2]);  zb[2] = fma2(ep1, q1.x, zb[2]);
            za[3] = fma2(ep0, q1.y, za[3]);  zb[3] = fma2(ep1, q1.y, zb[3]);
            za[4] = fma2(ep0, q2.x, za[4]);  zb[4] = fma2(ep1, q2.x, zb[4]);
            za[5] = fma2(ep0, q2.y, za[5]);  zb[5] = fma2(ep1, q2.y, zb[5]);
            za[6] = fma2(ep0, q3.x, za[6]);  zb[6] = fma2(ep1, q3.x, zb[6]);
            za[7] = fma2(ep0, q3.y, za[7]);  zb[7] = fma2(ep1, q3.y, zb[7]);
        }
    }

    // ---- normalize + store ----
    {
        const float inv0 = 1.0f / s0;
        const u64 iv0 = pack2(inv0, inv0);
        ulonglong2* o = reinterpret_cast<ulonglong2*>(out + (size_t)v0 * DVEC);
        #pragma unroll
        for (int i = 0; i < 4; i++) {
            ulonglong2 t;
            t.x = mul2(za[2 * i + 0], iv0);
            t.y = mul2(za[2 * i + 1], iv0);
            o[i] = t;
        }
    }
    if (haveB) {
        const float inv1 = 1.0f / s1;
        const u64 iv1 = pack2(inv1, inv1);
        ulonglong2* o = reinterpret_cast<ulonglong2*>(out + (size_t)v1 * DVEC);
        #pragma unroll
        for (int i = 0; i < 4; i++) {
            ulonglong2 t;
            t.x = mul2(zb[2 * i + 0], iv1);
            t.y = mul2(zb[2 * i + 1], iv1);
            o[i] = t;
        }
    }
}

extern "C" void kernel_launch(void* const* d_in, const int* in_sizes, int n_in,
                              void* d_out, int out_size) {
    const float* x   = (const float*)d_in[0];   // (64,8,32,32,16) f32
    const float* ref = (const float*)d_in[1];   // (64,16) f32
    float* out = (float*)d_out;

    const int nvec = in_sizes[0] / DVEC;        // 524288
    const int vecs_per_block = TPB * VPT;
    const int blocks = (nvec + vecs_per_block - 1) / vecs_per_block;
    stq_kernel<<<blocks, TPB>>>(x, ref, out, nvec);
}

// round 3
// speedup vs baseline: 4.3653x; 4.3653x over previous
#include <cuda_runtime.h>
#include <cuda_bf16.h>
#include <cstdint>

// soft_to_hard_quantize: N=524288 vectors of D=16 floats, M=64 codewords.
// logit_m (log2 domain) = 10*log2e*dot(x,r_m) - 5*log2e*||r_m||^2  (||x||^2 cancels)
// z = sum_m exp2(logit_m - max) * r_m / sum_m exp2(...)
//
// Codebook lives in __constant__ memory: all lanes index it uniformly, so the
// loads go down the uniform (LDCU/UR) path instead of the smem crossbar that
// bound the previous version.

#define MCODE 64
#define DVEC  16
#define TPB   256

typedef unsigned long long u64;

struct Codebook {
    float slog[MCODE][DVEC];  // 10*log2(e) * r_m[i]   (logit dot operand)
    float b2[MCODE];          // -5*log2(e) * ||r_m||^2
    float cw[MCODE][DVEC];    // raw r_m[i]            (z accumulation operand)
};

__device__   Codebook g_cb;   // staging, written by prep kernel
__constant__ Codebook c_cb;   // read by main kernel (uniform datapath)

__global__ void prep_kernel(const float* __restrict__ ref) {
    const int m = threadIdx.x;  // 64 threads
    float s = 0.0f;
    #pragma unroll
    for (int i = 0; i < DVEC; i++) {
        float r = ref[m * DVEC + i];
        g_cb.cw[m][i]   = r;
        g_cb.slog[m][i] = 14.426950408889634f * r;   // 10*log2(e)
        s = fmaf(r, r, s);
    }
    g_cb.b2[m] = -7.2134752044448169f * s;           // -5*log2(e)
}

__device__ __forceinline__ u64 fma2(u64 a, u64 b, u64 c) {
    u64 d;
    asm("fma.rn.f32x2 %0, %1, %2, %3;" : "=l"(d) : "l"(a), "l"(b), "l"(c));
    return d;
}
__device__ __forceinline__ u64 mul2(u64 a, u64 b) {
    u64 d;
    asm("mul.rn.f32x2 %0, %1, %2;" : "=l"(d) : "l"(a), "l"(b));
    return d;
}
__device__ __forceinline__ u64 pack2(float lo, float hi) {
    u64 r;
    asm("mov.b64 %0, {%1, %2};" : "=l"(r) : "f"(lo), "f"(hi));
    return r;
}
__device__ __forceinline__ void unpack2(u64 v, float& lo, float& hi) {
    asm("mov.b64 {%0, %1}, %2;" : "=f"(lo), "=f"(hi) : "l"(v));
}
__device__ __forceinline__ float ex2f(float x) {
    float r;
    asm("ex2.approx.ftz.f32 %0, %1;" : "=f"(r) : "f"(x));
    return r;
}
__device__ __forceinline__ u64 cpair(const float* p) {
    // Uniform-address constant load of a packed f32 pair.
    return *reinterpret_cast<const u64*>(p);
}

__global__ __launch_bounds__(TPB)
void stq_kernel(const float* __restrict__ x,
                float* __restrict__ out,
                int nvec) {
    const int v = blockIdx.x * TPB + threadIdx.x;
    if (v >= nvec) return;

    // Load this thread's 16-float vector as 8 packed pairs (4 x LDG.128).
    const ulonglong2* xin = reinterpret_cast<const ulonglong2*>(x + (size_t)v * DVEC);
    u64 xp[8];
    #pragma unroll
    for (int i = 0; i < 4; i++) {
        ulonglong2 t = xin[i];
        xp[2 * i + 0] = t.x;
        xp[2 * i + 1] = t.y;
    }

    // ---- Pass 1: logits (log2 domain), codebook from constant memory ----
    float l[MCODE];
    #pragma unroll 8
    for (int m = 0; m < MCODE; m++) {
        const float* s = c_cb.slog[m];
        u64 acc = fma2(xp[0], cpair(s + 0), 0ULL);
        acc = fma2(xp[1], cpair(s + 2),  acc);
        acc = fma2(xp[2], cpair(s + 4),  acc);
        acc = fma2(xp[3], cpair(s + 6),  acc);
        acc = fma2(xp[4], cpair(s + 8),  acc);
        acc = fma2(xp[5], cpair(s + 10), acc);
        acc = fma2(xp[6], cpair(s + 12), acc);
        acc = fma2(xp[7], cpair(s + 14), acc);
        float lo, hi;
        unpack2(acc, lo, hi);
        l[m] = (lo + hi) + c_cb.b2[m];
    }

    // ---- max over logits (4 parallel chains) ----
    float m0 = l[0], m1 = l[1], m2 = l[2], m3 = l[3];
    #pragma unroll
    for (int m = 4; m < MCODE; m += 4) {
        m0 = fmaxf(m0, l[m + 0]);
        m1 = fmaxf(m1, l[m + 1]);
        m2 = fmaxf(m2, l[m + 2]);
        m3 = fmaxf(m3, l[m + 3]);
    }
    const float mx = fmaxf(fmaxf(m0, m1), fmaxf(m2, m3));

    // ---- Pass 2: exp + weighted codeword accumulation ----
    float s0 = 0.0f, s1 = 0.0f, s2 = 0.0f, s3 = 0.0f;
    u64 zp[8];
    #pragma unroll
    for (int p = 0; p < 8; p++) zp[p] = 0ULL;

    #pragma unroll 8
    for (int m = 0; m < MCODE; m++) {
        const float e = ex2f(l[m] - mx);
        if ((m & 3) == 0) s0 += e;
        else if ((m & 3) == 1) s1 += e;
        else if ((m & 3) == 2) s2 += e;
        else s3 += e;
        const u64 ee = pack2(e, e);
        const float* w = c_cb.cw[m];
        zp[0] = fma2(ee, cpair(w + 0),  zp[0]);
        zp[1] = fma2(ee, cpair(w + 2),  zp[1]);
        zp[2] = fma2(ee, cpair(w + 4),  zp[2]);
        zp[3] = fma2(ee, cpair(w + 6),  zp[3]);
        zp[4] = fma2(ee, cpair(w + 8),  zp[4]);
        zp[5] = fma2(ee, cpair(w + 10), zp[5]);
        zp[6] = fma2(ee, cpair(w + 12), zp[6]);
        zp[7] = fma2(ee, cpair(w + 14), zp[7]);
    }

    const float inv = 1.0f / ((s0 + s1) + (s2 + s3));
    const u64 iv = pack2(inv, inv);

    ulonglong2* o = reinterpret_cast<ulonglong2*>(out + (size_t)v * DVEC);
    #pragma unroll
    for (int i = 0; i < 4; i++) {
        ulonglong2 t;
        t.x = mul2(zp[2 * i + 0], iv);
        t.y = mul2(zp[2 * i + 1], iv);
        o[i] = t;
    }
}

extern "C" void kernel_launch(void* const* d_in, const int* in_sizes, int n_in,
                              void* d_out, int out_size) {
    const float* x   = (const float*)d_in[0];   // (64,8,32,32,16) f32
    const float* ref = (const float*)d_in[1];   // (64,16) f32
    float* out = (float*)d_out;

    // 1) Prep: scale codebook + biases into staging global.
    prep_kernel<<<1, MCODE>>>(ref);

    // 2) Staging -> __constant__ (device-to-device async copy; capturable).
    void *pc = nullptr, *pg = nullptr;
    cudaGetSymbolAddress(&pc, c_cb);
    cudaGetSymbolAddress(&pg, g_cb);
    cudaMemcpyAsync(pc, pg, sizeof(Codebook), cudaMemcpyDeviceToDevice, 0);

    // 3) Main kernel.
    const int nvec = in_sizes[0] / DVEC;        // 524288
    const int blocks = (nvec + TPB - 1) / TPB;
    stq_kernel<<<blocks, TPB>>>(x, out, nvec);
}

// round 4
// speedup vs baseline: 6.1590x; 1.4109x over previous
#include <cuda_runtime.h>
#include <cuda_bf16.h>
#include <cstdint>

// soft_to_hard_quantize: N=524288 vectors of D=16 floats, M=64 codewords.
// logit_m (log2 domain) = 10*log2e*dot(x,r_m) - 5*log2e*||r_m||^2  (||x||^2 cancels)
// z = sum_m exp2(logit_m - max) * r_m / sum_m exp2(...)
//
// Codebook in __constant__ memory (uniform datapath, no smem crossbar traffic).
// Both m-loops are FULLY unrolled so the 64-logit array stays in registers —
// partial unroll previously demoted it to local memory (spill traffic ~2x I/O).

#define MCODE 64
#define DVEC  16
#define TPB   256

typedef unsigned long long u64;

struct Codebook {
    float slog[MCODE][DVEC];  // 10*log2(e) * r_m[i]   (logit dot operand)
    float b2[MCODE];          // -5*log2(e) * ||r_m||^2
    float cw[MCODE][DVEC];    // raw r_m[i]            (z accumulation operand)
};

__device__   Codebook g_cb;   // staging, written by prep kernel
__constant__ Codebook c_cb;   // read by main kernel

__global__ void prep_kernel(const float* __restrict__ ref) {
    const int m = threadIdx.x;  // 64 threads
    float s = 0.0f;
    #pragma unroll
    for (int i = 0; i < DVEC; i++) {
        float r = ref[m * DVEC + i];
        g_cb.cw[m][i]   = r;
        g_cb.slog[m][i] = 14.426950408889634f * r;   // 10*log2(e)
        s = fmaf(r, r, s);
    }
    g_cb.b2[m] = -7.2134752044448169f * s;           // -5*log2(e)
}

__device__ __forceinline__ u64 fma2(u64 a, u64 b, u64 c) {
    u64 d;
    asm("fma.rn.f32x2 %0, %1, %2, %3;" : "=l"(d) : "l"(a), "l"(b), "l"(c));
    return d;
}
__device__ __forceinline__ u64 mul2(u64 a, u64 b) {
    u64 d;
    asm("mul.rn.f32x2 %0, %1, %2;" : "=l"(d) : "l"(a), "l"(b));
    return d;
}
__device__ __forceinline__ u64 pack2(float lo, float hi) {
    u64 r;
    asm("mov.b64 %0, {%1, %2};" : "=l"(r) : "f"(lo), "f"(hi));
    return r;
}
__device__ __forceinline__ void unpack2(u64 v, float& lo, float& hi) {
    asm("mov.b64 {%0, %1}, %2;" : "=f"(lo), "=f"(hi) : "l"(v));
}
__device__ __forceinline__ float ex2f(float x) {
    float r;
    asm("ex2.approx.ftz.f32 %0, %1;" : "=f"(r) : "f"(x));
    return r;
}
__device__ __forceinline__ u64 cpair(const float* p) {
    return *reinterpret_cast<const u64*>(p);
}

__global__ __launch_bounds__(TPB)
void stq_kernel(const float* __restrict__ x,
                float* __restrict__ out,
                int nvec) {
    const int v = blockIdx.x * TPB + threadIdx.x;
    if (v >= nvec) return;

    // Load this thread's 16-float vector as 8 packed pairs (4 x LDG.128).
    const ulonglong2* xin = reinterpret_cast<const ulonglong2*>(x + (size_t)v * DVEC);
    u64 xp[8];
    #pragma unroll
    for (int i = 0; i < 4; i++) {
        ulonglong2 t = xin[i];
        xp[2 * i + 0] = t.x;
        xp[2 * i + 1] = t.y;
    }

    // ---- Pass 1: logits (log2 domain). FULL unroll -> l[] in registers. ----
    float l[MCODE];
    #pragma unroll
    for (int m = 0; m < MCODE; m++) {
        const float* s = c_cb.slog[m];
        u64 acc = fma2(xp[0], cpair(s + 0), 0ULL);
        acc = fma2(xp[1], cpair(s + 2),  acc);
        acc = fma2(xp[2], cpair(s + 4),  acc);
        acc = fma2(xp[3], cpair(s + 6),  acc);
        acc = fma2(xp[4], cpair(s + 8),  acc);
        acc = fma2(xp[5], cpair(s + 10), acc);
        acc = fma2(xp[6], cpair(s + 12), acc);
        acc = fma2(xp[7], cpair(s + 14), acc);
        float lo, hi;
        unpack2(acc, lo, hi);
        l[m] = (lo + hi) + c_cb.b2[m];
    }

    // ---- max over logits (4 parallel chains) ----
    float m0 = l[0], m1 = l[1], m2 = l[2], m3 = l[3];
    #pragma unroll
    for (int m = 4; m < MCODE; m += 4) {
        m0 = fmaxf(m0, l[m + 0]);
        m1 = fmaxf(m1, l[m + 1]);
        m2 = fmaxf(m2, l[m + 2]);
        m3 = fmaxf(m3, l[m + 3]);
    }
    const float mx = fmaxf(fmaxf(m0, m1), fmaxf(m2, m3));

    // ---- Pass 2: exp + weighted codeword accumulation. FULL unroll. ----
    float s0 = 0.0f, s1 = 0.0f, s2 = 0.0f, s3 = 0.0f;
    u64 zp[8];
    #pragma unroll
    for (int p = 0; p < 8; p++) zp[p] = 0ULL;

    #pragma unroll
    for (int m = 0; m < MCODE; m++) {
        const float e = ex2f(l[m] - mx);
        if ((m & 3) == 0) s0 += e;
        else if ((m & 3) == 1) s1 += e;
        else if ((m & 3) == 2) s2 += e;
        else s3 += e;
        const u64 ee = pack2(e, e);
        const float* w = c_cb.cw[m];
        zp[0] = fma2(ee, cpair(w + 0),  zp[0]);
        zp[1] = fma2(ee, cpair(w + 2),  zp[1]);
        zp[2] = fma2(ee, cpair(w + 4),  zp[2]);
        zp[3] = fma2(ee, cpair(w + 6),  zp[3]);
        zp[4] = fma2(ee, cpair(w + 8),  zp[4]);
        zp[5] = fma2(ee, cpair(w + 10), zp[5]);
        zp[6] = fma2(ee, cpair(w + 12), zp[6]);
        zp[7] = fma2(ee, cpair(w + 14), zp[7]);
    }

    const float inv = 1.0f / ((s0 + s1) + (s2 + s3));
    const u64 iv = pack2(inv, inv);

    ulonglong2* o = reinterpret_cast<ulonglong2*>(out + (size_t)v * DVEC);
    #pragma unroll
    for (int i = 0; i < 4; i++) {
        ulonglong2 t;
        t.x = mul2(zp[2 * i + 0], iv);
        t.y = mul2(zp[2 * i + 1], iv);
        o[i] = t;
    }
}

extern "C" void kernel_launch(void* const* d_in, const int* in_sizes, int n_in,
                              void* d_out, int out_size) {
    const float* x   = (const float*)d_in[0];   // (64,8,32,32,16) f32
    const float* ref = (const float*)d_in[1];   // (64,16) f32
    float* out = (float*)d_out;

    // 1) Prep: scale codebook + biases into staging global.
    prep_kernel<<<1, MCODE>>>(ref);

    // 2) Staging -> __constant__ (device-to-device async copy; capturable).
    void *pc = nullptr, *pg = nullptr;
    cudaGetSymbolAddress(&pc, c_cb);
    cudaGetSymbolAddress(&pg, g_cb);
    cudaMemcpyAsync(pc, pg, sizeof(Codebook), cudaMemcpyDeviceToDevice, 0);

    // 3) Main kernel.
    const int nvec = in_sizes[0] / DVEC;        // 524288
    const int blocks = (nvec + TPB - 1) / TPB;
    stq_kernel<<<blocks, TPB>>>(x, out, nvec);
}